// round 4
// baseline (speedup 1.0000x reference)
#include <cuda_runtime.h>
#include <math.h>

#define B_  32
#define H_  512
#define W_  512
#define DEG 0.017453292519943295f
#define TW  32
#define TH  16
#define NT  256
#define SBUF_FLOATS 12256   // 48KB minus params

// Per-batch params: M[9], gamma, Mc[9], apply, cx, cy, cwHalf, chHalf
__device__ float g_params[B_ * 32];

__device__ __forceinline__ void mat3_mul(const float* A, const float* Bm, float* C) {
#pragma unroll
    for (int i = 0; i < 3; i++)
#pragma unroll
        for (int j = 0; j < 3; j++) {
            float s = 0.f;
#pragma unroll
            for (int k = 0; k < 3; k++) s += A[i * 3 + k] * Bm[k * 3 + j];
            C[i * 3 + j] = s;
        }
}

__global__ void param_kernel(const float* __restrict__ geom_u,
                             const float* __restrict__ color_u,
                             const float* __restrict__ cutout_u) {
    int b = threadIdx.x;
    if (b >= B_) return;

    const float* g = geom_u + b * 8;
    float flip = g[0] > 0.5f ? -1.f : 1.f;
    float tilt = (g[1] * 2.f - 1.f) * (15.f * DEG);
    float pan  = (g[2] * 2.f - 1.f) * (15.f * DEG);
    float rot  = (g[3] * 2.f - 1.f) * (15.f * DEG);
    float sc   = 1.f + (g[4] * 2.f - 1.f) * 0.1f;
    float tx   = (g[5] * 2.f - 1.f) * 0.2f;
    float ty   = (g[6] * 2.f - 1.f) * 0.2f;

    float F[9]  = {flip, 0, 0, 0, 1, 0, 0, 0, 1};
    float ct = cosf(tilt), st = sinf(tilt);
    float Rx[9] = {1, 0, 0, 0, ct, -st, 0, st, ct};
    float cp = cosf(pan), sp = sinf(pan);
    float Ry[9] = {cp, 0, sp, 0, 1, 0, -sp, 0, cp};
    float cr = cosf(rot), sr = sinf(rot);
    float RS[9] = {sc * cr, -sc * sr, 0, sc * sr, sc * cr, 0, 0, 0, 1};
    float T[9]  = {1, 0, tx, 0, 1, ty, 0, 0, 1};

    float t0[9], t1[9], t2[9], M[9];
    mat3_mul(Ry, F, t0);
    mat3_mul(Rx, t0, t1);
    mat3_mul(RS, t1, t2);
    mat3_mul(T, t2, M);

    const float* c = color_u + b * 4;
    float theta = (c[0] * 2.f - 1.f) * (10.f * DEG);
    float cth = cosf(theta), sth = sinf(theta);
    const float a = 0.5773502691896258f;
    float K[9] = {0, -a, a, a, 0, -a, -a, a, 0};
    float Rh[9];
#pragma unroll
    for (int i = 0; i < 3; i++)
#pragma unroll
        for (int j = 0; j < 3; j++)
            Rh[i * 3 + j] = cth * (i == j ? 1.f : 0.f) + sth * K[i * 3 + j] +
                            (1.f - cth) * (1.f / 3.f);
    float sat = 1.f + (c[1] * 2.f - 1.f) * 0.4f;
    const float lum[3] = {0.299f, 0.587f, 0.114f};
    float Sm[9];
#pragma unroll
    for (int i = 0; i < 3; i++)
#pragma unroll
        for (int j = 0; j < 3; j++)
            Sm[i * 3 + j] = sat * (i == j ? 1.f : 0.f) + (1.f - sat) * lum[j];
    float bright = 1.f + (c[2] * 2.f - 1.f) * 0.1f;
    float Mc[9];
    mat3_mul(Sm, Rh, Mc);
#pragma unroll
    for (int i = 0; i < 9; i++) Mc[i] *= bright;
    float gamma = 1.f + (c[3] * 2.f - 1.f) * 0.2f;

    const float* cu = cutout_u + b * 5;
    float* p = g_params + b * 32;
#pragma unroll
    for (int i = 0; i < 9; i++) p[i] = M[i];
    p[9] = gamma;
#pragma unroll
    for (int i = 0; i < 9; i++) p[10 + i] = Mc[i];
    p[19] = (cu[0] < 0.5f) ? 1.f : 0.f;
    p[20] = cu[1];
    p[21] = cu[2];
    p[22] = (0.3f + 0.2f * cu[3]) * 0.5f;
    p[23] = (0.3f + 0.2f * cu[4]) * 0.5f;
}

__global__ __launch_bounds__(NT) void augment_tiled(
    const float* __restrict__ images, float* __restrict__ out) {
    __shared__ float sp[24];
    __shared__ float sbuf[SBUF_FLOATS];

    int jx0 = blockIdx.x * TW;
    int iy0 = blockIdx.y * TH;
    int b   = blockIdx.z;
    int tid = threadIdx.x;

    if (tid < 24) sp[tid] = g_params[b * 32 + tid];
    __syncthreads();

    // ---- source bbox from tile corners (projective: extrema at corners) ----
    const float c2 = 2.f / 511.f;
    float xs2[2] = {jx0 * c2 - 1.f, (jx0 + TW - 1) * c2 - 1.f};
    float ys2[2] = {iy0 * c2 - 1.f, (iy0 + TH - 1) * c2 - 1.f};
    float minpx = 1e30f, maxpx = -1e30f, minpy = 1e30f, maxpy = -1e30f;
#pragma unroll
    for (int cy = 0; cy < 2; cy++)
#pragma unroll
        for (int cx = 0; cx < 2; cx++) {
            float X = xs2[cx], Y = ys2[cy];
            float sxc = sp[0] * X + sp[1] * Y + sp[2];
            float syc = sp[3] * X + sp[4] * Y + sp[5];
            float szc = sp[6] * X + sp[7] * Y + sp[8];
            float iv = 1.f / szc;
            float ppx = (sxc * iv + 1.f) * 255.5f;
            float ppy = (syc * iv + 1.f) * 255.5f;
            minpx = fminf(minpx, ppx); maxpx = fmaxf(maxpx, ppx);
            minpy = fminf(minpy, ppy); maxpy = fmaxf(maxpy, ppy);
        }
    int bx0 = min(max((int)floorf(minpx) - 1, 0), 511);
    int bx1 = min(max((int)floorf(maxpx) + 2, 0), 511);
    int by0 = min(max((int)floorf(minpy) - 1, 0), 511);
    int by1 = min(max((int)floorf(maxpy) + 2, 0), 511);
    bx0 &= ~3;  // 16B-align row starts ((bx0*3)%4==0)

    int wpix  = bx1 - bx0 + 1;
    int hrows = by1 - by0 + 1;
    int rowf  = wpix * 3;
    int rowS  = (rowf + 3) & ~3;      // smem row stride (float4 aligned)
    bool staged = (hrows * rowS <= SBUF_FLOATS);
    int bOff = b << 18;

    // ---- stage source footprint into smem (coalesced float4) ----
    if (staged) {
        int rowS4  = rowS >> 2;
        int n4     = rowf >> 2;       // full float4 per row
        int total4 = hrows * rowS4;
        for (int idx = tid; idx < total4; idx += NT) {
            int r = idx / rowS4;
            int c = idx - r * rowS4;
            const float* src = images + ((size_t)(bOff + (by0 + r) * W_ + bx0)) * 3;
            float4 v;
            if (c < n4) {
                v = __ldg((const float4*)src + c);
            } else {
                float tmp[4] = {0.f, 0.f, 0.f, 0.f};
                for (int t = 4 * c; t < rowf; t++) tmp[t - 4 * c] = __ldg(src + t);
                v = make_float4(tmp[0], tmp[1], tmp[2], tmp[3]);
            }
            ((float4*)sbuf)[idx] = v;
        }
    }
    __syncthreads();

    // ---- per-pixel work: 2 pixels per thread (rows ty, ty+8) ----
    float res[2][3];
    int txl = tid & 31;
    int tyb = tid >> 5;
    int jx  = jx0 + txl;
    float X = jx * c2 - 1.f;
    float gamma = sp[9];

#pragma unroll
    for (int k = 0; k < 2; k++) {
        int iy = iy0 + tyb + k * 8;
        float Y = iy * c2 - 1.f;

        float sx = sp[0] * X + sp[1] * Y + sp[2];
        float sy = sp[3] * X + sp[4] * Y + sp[5];
        float sz = sp[6] * X + sp[7] * Y + sp[8];
        float inv = 1.f / sz;
        float px = (sx * inv + 1.f) * 255.5f;
        float py = (sy * inv + 1.f) * 255.5f;

        bool valid = (px >= 0.f) & (px <= 511.f) & (py >= 0.f) & (py <= 511.f);
        float fx0 = fminf(fmaxf(floorf(px), 0.f), 511.f);
        float fy0 = fminf(fmaxf(floorf(py), 0.f), 511.f);
        float wx = px - fx0;
        float wy = py - fy0;
        int x0 = (int)fx0, y0 = (int)fy0;
        int x1 = min(x0 + 1, W_ - 1);
        int y1 = min(y0 + 1, H_ - 1);

        float w00 = (1.f - wx) * (1.f - wy);
        float w01 = wx * (1.f - wy);
        float w10 = (1.f - wx) * wy;
        float w11 = wx * wy;
        float vm = valid ? 1.f : 0.f;

        float r3[3];
        if (staged) {
            int i00 = (y0 - by0) * rowS + (x0 - bx0) * 3;
            int dxx = (x1 - x0) * 3;
            int dyy = (y1 - y0) * rowS;
#pragma unroll
            for (int ch = 0; ch < 3; ch++) {
                float a00 = sbuf[i00 + ch];
                float a01 = sbuf[i00 + dxx + ch];
                float a10 = sbuf[i00 + dyy + ch];
                float a11 = sbuf[i00 + dyy + dxx + ch];
                float s = a00 * w00 + a01 * w01 + a10 * w10 + a11 * w11;
                s *= vm;
                s = fminf(fmaxf(s, 0.f), 1.f);
                r3[ch] = exp2f(gamma * __log2f(s));
            }
        } else {
            const float* q00 = images + (size_t)(bOff + y0 * W_ + x0) * 3;
            const float* q01 = images + (size_t)(bOff + y0 * W_ + x1) * 3;
            const float* q10 = images + (size_t)(bOff + y1 * W_ + x0) * 3;
            const float* q11 = images + (size_t)(bOff + y1 * W_ + x1) * 3;
#pragma unroll
            for (int ch = 0; ch < 3; ch++) {
                float s = __ldg(q00 + ch) * w00 + __ldg(q01 + ch) * w01 +
                          __ldg(q10 + ch) * w10 + __ldg(q11 + ch) * w11;
                s *= vm;
                s = fminf(fmaxf(s, 0.f), 1.f);
                r3[ch] = exp2f(gamma * __log2f(s));
            }
        }

        float o0 = sp[10] * r3[0] + sp[11] * r3[1] + sp[12] * r3[2];
        float o1 = sp[13] * r3[0] + sp[14] * r3[1] + sp[15] * r3[2];
        float o2 = sp[16] * r3[0] + sp[17] * r3[1] + sp[18] * r3[2];
        o0 = fminf(fmaxf(o0, 0.f), 1.f);
        o1 = fminf(fmaxf(o1, 0.f), 1.f);
        o2 = fminf(fmaxf(o2, 0.f), 1.f);

        float gx = (float)jx * (1.f / 511.f);
        float gy = (float)iy * (1.f / 511.f);
        bool cut = (sp[19] != 0.f) & (fabsf(gx - sp[20]) < sp[22]) &
                   (fabsf(gy - sp[21]) < sp[23]);
        if (cut) { o0 = 0.f; o1 = 0.f; o2 = 0.f; }
        res[k][0] = o0; res[k][1] = o1; res[k][2] = o2;
    }

    // ---- stage outputs in smem, then coalesced float4 store ----
    __syncthreads();   // smem reads done; safe to overwrite
#pragma unroll
    for (int k = 0; k < 2; k++) {
        int p = (tyb + k * 8) * TW + txl;   // tile-local pixel
        sbuf[p * 3 + 0] = res[k][0];
        sbuf[p * 3 + 1] = res[k][1];
        sbuf[p * 3 + 2] = res[k][2];
    }
    __syncthreads();

    // 16 tile rows x 24 float4 = 384 float4
    for (int v = tid; v < (TH * TW * 3) / 4; v += NT) {
        int tr = v / 24;
        int cc = v - tr * 24;
        float4 val = ((const float4*)sbuf)[v];
        size_t o4 = (((size_t)(b * H_ + iy0 + tr) * W_ + jx0) * 3) >> 2;
        ((float4*)out)[o4 + cc] = val;
    }
}

extern "C" void kernel_launch(void* const* d_in, const int* in_sizes, int n_in,
                              void* d_out, int out_size) {
    const float* images   = (const float*)d_in[0];
    const float* geom_u   = (const float*)d_in[1];
    const float* color_u  = (const float*)d_in[2];
    const float* cutout_u = (const float*)d_in[3];
    float* out = (float*)d_out;

    param_kernel<<<1, 32>>>(geom_u, color_u, cutout_u);
    dim3 grid(W_ / TW, H_ / TH, B_);
    augment_tiled<<<grid, NT>>>(images, out);
}

// round 5
// speedup vs baseline: 1.2676x; 1.2676x over previous
#include <cuda_runtime.h>
#include <math.h>

#define B_  32
#define H_  512
#define W_  512
#define DEG 0.017453292519943295f
#define TW  32
#define TH  32
#define NT  512
#define SMEM_FLOATS 13312   // 52KB dynamic

__device__ float g_params[B_ * 32];

__device__ __forceinline__ float frcp(float x) {
    float y;
    asm("rcp.approx.f32 %0, %1;" : "=f"(y) : "f"(x));
    return y;
}

__device__ __forceinline__ void mat3_mul(const float* A, const float* Bm, float* C) {
#pragma unroll
    for (int i = 0; i < 3; i++)
#pragma unroll
        for (int j = 0; j < 3; j++) {
            float s = 0.f;
#pragma unroll
            for (int k = 0; k < 3; k++) s += A[i * 3 + k] * Bm[k * 3 + j];
            C[i * 3 + j] = s;
        }
}

__global__ void param_kernel(const float* __restrict__ geom_u,
                             const float* __restrict__ color_u,
                             const float* __restrict__ cutout_u) {
    int b = threadIdx.x;
    if (b >= B_) return;

    const float* g = geom_u + b * 8;
    float flip = g[0] > 0.5f ? -1.f : 1.f;
    float tilt = (g[1] * 2.f - 1.f) * (15.f * DEG);
    float pan  = (g[2] * 2.f - 1.f) * (15.f * DEG);
    float rot  = (g[3] * 2.f - 1.f) * (15.f * DEG);
    float sc   = 1.f + (g[4] * 2.f - 1.f) * 0.1f;
    float tx   = (g[5] * 2.f - 1.f) * 0.2f;
    float ty   = (g[6] * 2.f - 1.f) * 0.2f;

    float F[9]  = {flip, 0, 0, 0, 1, 0, 0, 0, 1};
    float ct = cosf(tilt), st = sinf(tilt);
    float Rx[9] = {1, 0, 0, 0, ct, -st, 0, st, ct};
    float cp = cosf(pan), sp = sinf(pan);
    float Ry[9] = {cp, 0, sp, 0, 1, 0, -sp, 0, cp};
    float cr = cosf(rot), sr = sinf(rot);
    float RS[9] = {sc * cr, -sc * sr, 0, sc * sr, sc * cr, 0, 0, 0, 1};
    float T[9]  = {1, 0, tx, 0, 1, ty, 0, 0, 1};

    float t0[9], t1[9], t2[9], M[9];
    mat3_mul(Ry, F, t0);
    mat3_mul(Rx, t0, t1);
    mat3_mul(RS, t1, t2);
    mat3_mul(T, t2, M);

    const float* c = color_u + b * 4;
    float theta = (c[0] * 2.f - 1.f) * (10.f * DEG);
    float cth = cosf(theta), sth = sinf(theta);
    const float a = 0.5773502691896258f;
    float K[9] = {0, -a, a, a, 0, -a, -a, a, 0};
    float Rh[9];
#pragma unroll
    for (int i = 0; i < 3; i++)
#pragma unroll
        for (int j = 0; j < 3; j++)
            Rh[i * 3 + j] = cth * (i == j ? 1.f : 0.f) + sth * K[i * 3 + j] +
                            (1.f - cth) * (1.f / 3.f);
    float sat = 1.f + (c[1] * 2.f - 1.f) * 0.4f;
    const float lum[3] = {0.299f, 0.587f, 0.114f};
    float Sm[9];
#pragma unroll
    for (int i = 0; i < 3; i++)
#pragma unroll
        for (int j = 0; j < 3; j++)
            Sm[i * 3 + j] = sat * (i == j ? 1.f : 0.f) + (1.f - sat) * lum[j];
    float bright = 1.f + (c[2] * 2.f - 1.f) * 0.1f;
    float Mc[9];
    mat3_mul(Sm, Rh, Mc);
#pragma unroll
    for (int i = 0; i < 9; i++) Mc[i] *= bright;
    float gamma = 1.f + (c[3] * 2.f - 1.f) * 0.2f;

    const float* cu = cutout_u + b * 5;
    float* p = g_params + b * 32;
#pragma unroll
    for (int i = 0; i < 9; i++) p[i] = M[i];
    p[9] = gamma;
#pragma unroll
    for (int i = 0; i < 9; i++) p[10 + i] = Mc[i];
    p[19] = (cu[0] < 0.5f) ? 1.f : 0.f;
    p[20] = cu[1];
    p[21] = cu[2];
    p[22] = (0.3f + 0.2f * cu[3]) * 0.5f;
    p[23] = (0.3f + 0.2f * cu[4]) * 0.5f;
}

__global__ __launch_bounds__(NT) void augment_tiled(
    const float* __restrict__ images, float* __restrict__ out) {
    extern __shared__ float sbuf[];
    __shared__ float sp[24];

    int jx0 = blockIdx.x * TW;
    int iy0 = blockIdx.y * TH;
    int b   = blockIdx.z;
    int tid = threadIdx.x;
    int lane = tid & 31;
    int wid  = tid >> 5;

    if (tid < 24) sp[tid] = g_params[b * 32 + tid];
    __syncthreads();

    // ---- source bbox from tile corners (fractional-linear => corner extrema) ----
    const float c2 = 2.f / 511.f;
    float xs2[2] = {jx0 * c2 - 1.f, (jx0 + TW - 1) * c2 - 1.f};
    float ys2[2] = {iy0 * c2 - 1.f, (iy0 + TH - 1) * c2 - 1.f};
    float minpx = 1e30f, maxpx = -1e30f, minpy = 1e30f, maxpy = -1e30f;
#pragma unroll
    for (int cy = 0; cy < 2; cy++)
#pragma unroll
        for (int cx = 0; cx < 2; cx++) {
            float X = xs2[cx], Y = ys2[cy];
            float sxc = sp[0] * X + sp[1] * Y + sp[2];
            float syc = sp[3] * X + sp[4] * Y + sp[5];
            float szc = sp[6] * X + sp[7] * Y + sp[8];
            float iv = frcp(szc);
            float ppx = (sxc * iv + 1.f) * 255.5f;
            float ppy = (syc * iv + 1.f) * 255.5f;
            minpx = fminf(minpx, ppx); maxpx = fmaxf(maxpx, ppx);
            minpy = fminf(minpy, ppy); maxpy = fmaxf(maxpy, ppy);
        }
    int bx0 = min(max((int)floorf(minpx) - 1, 0), 511);
    int bx1 = min(max((int)floorf(maxpx) + 2, 0), 511);
    int by0 = min(max((int)floorf(minpy) - 1, 0), 511);
    int by1 = min(max((int)floorf(maxpy) + 2, 0), 511);
    bx0 &= ~3;                          // row base 16B-aligned (3*bx0 % 4 == 0)

    int wpix  = bx1 - bx0 + 1;
    int hrows = by1 - by0 + 1;
    int rowf  = wpix * 3;
    int rowS  = (rowf + 3) & ~3;        // smem row stride in floats
    int rowf4 = (rowf + 3) >> 2;        // float4 per row (never OOB: see note)
    bool staged = (hrows * rowS <= SMEM_FLOATS);
    int bOff = b << 18;

    // ---- stage footprint: warp per row, lanes stride float4 (no divides) ----
    if (staged) {
        const float* srcBase = images + (size_t)(bOff + by0 * W_ + bx0) * 3;
        for (int r = wid; r < hrows; r += NT / 32) {
            const float4* s4 = (const float4*)(srcBase + r * (W_ * 3));
            float4* d4 = (float4*)(sbuf + r * rowS);
            for (int c = lane; c < rowf4; c += 32) d4[c] = __ldg(s4 + c);
        }
    }
    __syncthreads();

    // ---- 2 px per thread: (lane, wid) and (lane, wid+16) ----
    int jx = jx0 + lane;
    float X = jx * c2 - 1.f;
    float gamma = sp[9];
    // x-constant partials of the affine rows
    float sxX = sp[0] * X + sp[2];
    float syX = sp[3] * X + sp[5];
    float szX = sp[6] * X + sp[8];
    float gx = (float)jx * (1.f / 511.f);
    bool cutx = (sp[19] != 0.f) & (fabsf(gx - sp[20]) < sp[22]);

#pragma unroll
    for (int k = 0; k < 2; k++) {
        int iy = iy0 + wid + k * 16;
        float Y = iy * c2 - 1.f;

        float sx = sp[1] * Y + sxX;
        float sy = sp[4] * Y + syX;
        float sz = sp[7] * Y + szX;
        float inv = frcp(sz);
        float px = (sx * inv + 1.f) * 255.5f;
        float py = (sy * inv + 1.f) * 255.5f;

        bool valid = (px >= 0.f) & (px <= 511.f) & (py >= 0.f) & (py <= 511.f);
        float fx0 = fminf(fmaxf(floorf(px), 0.f), 511.f);
        float fy0 = fminf(fmaxf(floorf(py), 0.f), 511.f);
        float wx = px - fx0;
        float wy = py - fy0;
        int x0 = (int)fx0, y0 = (int)fy0;
        int dx3 = (x0 < 511) ? 3 : 0;       // (x1-x0)*3

        float f00[3], f01[3], f10[3], f11[3];
        if (staged) {
            int dyS = (y0 < 511) ? rowS : 0;
            const float* A = sbuf + (y0 - by0) * rowS + (x0 - bx0) * 3;
            const float* Bt = A + dyS;
#pragma unroll
            for (int ch = 0; ch < 3; ch++) {
                f00[ch] = A[ch];
                f01[ch] = A[dx3 + ch];
                f10[ch] = Bt[ch];
                f11[ch] = Bt[dx3 + ch];
            }
        } else {
            int dy3 = (y0 < 511) ? (W_ * 3) : 0;
            const float* A = images + (size_t)(bOff + y0 * W_ + x0) * 3;
            const float* Bt = A + dy3;
#pragma unroll
            for (int ch = 0; ch < 3; ch++) {
                f00[ch] = __ldg(A + ch);
                f01[ch] = __ldg(A + dx3 + ch);
                f10[ch] = __ldg(Bt + ch);
                f11[ch] = __ldg(Bt + dx3 + ch);
            }
        }

        float w00 = (1.f - wx) * (1.f - wy);
        float w01 = wx * (1.f - wy);
        float w10 = (1.f - wx) * wy;
        float w11 = wx * wy;
        float vm = valid ? 1.f : 0.f;

        float r3[3];
#pragma unroll
        for (int ch = 0; ch < 3; ch++) {
            float s = f00[ch] * w00 + f01[ch] * w01 + f10[ch] * w10 + f11[ch] * w11;
            s *= vm;
            s = fminf(fmaxf(s, 0.f), 1.f);
            r3[ch] = exp2f(gamma * __log2f(s));   // 0 -> 0, matches 0^g
        }

        float o0 = sp[10] * r3[0] + sp[11] * r3[1] + sp[12] * r3[2];
        float o1 = sp[13] * r3[0] + sp[14] * r3[1] + sp[15] * r3[2];
        float o2 = sp[16] * r3[0] + sp[17] * r3[1] + sp[18] * r3[2];
        o0 = fminf(fmaxf(o0, 0.f), 1.f);
        o1 = fminf(fmaxf(o1, 0.f), 1.f);
        o2 = fminf(fmaxf(o2, 0.f), 1.f);

        float gy = (float)iy * (1.f / 511.f);
        bool cut = cutx & (fabsf(gy - sp[21]) < sp[23]);
        if (cut) { o0 = 0.f; o1 = 0.f; o2 = 0.f; }

        float* op = out + (size_t)((b * H_ + iy) * W_ + jx) * 3;
        op[0] = o0;
        op[1] = o1;
        op[2] = o2;
    }
}

extern "C" void kernel_launch(void* const* d_in, const int* in_sizes, int n_in,
                              void* d_out, int out_size) {
    const float* images   = (const float*)d_in[0];
    const float* geom_u   = (const float*)d_in[1];
    const float* color_u  = (const float*)d_in[2];
    const float* cutout_u = (const float*)d_in[3];
    float* out = (float*)d_out;

    static int configured = 0;
    if (!configured) {
        cudaFuncSetAttribute(augment_tiled,
                             cudaFuncAttributeMaxDynamicSharedMemorySize,
                             SMEM_FLOATS * 4);
        configured = 1;
    }

    param_kernel<<<1, 32>>>(geom_u, color_u, cutout_u);
    dim3 grid(W_ / TW, H_ / TH, B_);
    augment_tiled<<<grid, NT, SMEM_FLOATS * 4>>>(images, out);
}

// round 7
// speedup vs baseline: 2.0040x; 1.5809x over previous
#include <cuda_runtime.h>
#include <math.h>

#define B_  32
#define H_  512
#define W_  512
#define DEG 0.017453292519943295f
#define NT  256     // 8 warps; warp w handles rows [w*4, w*4+4) of a 32x32 tile

__device__ float g_params[B_ * 32];

__device__ __forceinline__ float frcp_nr(float x) {
    float y;
    asm("rcp.approx.f32 %0, %1;" : "=f"(y) : "f"(x));
    // one Newton step: y*(2 - x*y)  -> ~full fp32 precision
    return y * fmaf(-x, y, 2.0f);
}
__device__ __forceinline__ float flg2(float x) {
    float y;
    asm("lg2.approx.f32 %0, %1;" : "=f"(y) : "f"(x));
    return y;
}
__device__ __forceinline__ float fex2(float x) {
    float y;
    asm("ex2.approx.f32 %0, %1;" : "=f"(y) : "f"(x));
    return y;
}

__device__ __forceinline__ void mat3_mul(const float* A, const float* Bm, float* C) {
#pragma unroll
    for (int i = 0; i < 3; i++)
#pragma unroll
        for (int j = 0; j < 3; j++) {
            float s = 0.f;
#pragma unroll
            for (int k = 0; k < 3; k++) s += A[i * 3 + k] * Bm[k * 3 + j];
            C[i * 3 + j] = s;
        }
}

__global__ void param_kernel(const float* __restrict__ geom_u,
                             const float* __restrict__ color_u,
                             const float* __restrict__ cutout_u) {
    int b = threadIdx.x;
    if (b >= B_) return;

    const float* g = geom_u + b * 8;
    float flip = g[0] > 0.5f ? -1.f : 1.f;
    float tilt = (g[1] * 2.f - 1.f) * (15.f * DEG);
    float pan  = (g[2] * 2.f - 1.f) * (15.f * DEG);
    float rot  = (g[3] * 2.f - 1.f) * (15.f * DEG);
    float sc   = 1.f + (g[4] * 2.f - 1.f) * 0.1f;
    float tx   = (g[5] * 2.f - 1.f) * 0.2f;
    float ty   = (g[6] * 2.f - 1.f) * 0.2f;

    float F[9]  = {flip, 0, 0, 0, 1, 0, 0, 0, 1};
    float ct = cosf(tilt), st = sinf(tilt);
    float Rx[9] = {1, 0, 0, 0, ct, -st, 0, st, ct};
    float cp = cosf(pan), sp = sinf(pan);
    float Ry[9] = {cp, 0, sp, 0, 1, 0, -sp, 0, cp};
    float cr = cosf(rot), sr = sinf(rot);
    float RS[9] = {sc * cr, -sc * sr, 0, sc * sr, sc * cr, 0, 0, 0, 1};
    float T[9]  = {1, 0, tx, 0, 1, ty, 0, 0, 1};

    float t0[9], t1[9], t2[9], M[9];
    mat3_mul(Ry, F, t0);
    mat3_mul(Rx, t0, t1);
    mat3_mul(RS, t1, t2);
    mat3_mul(T, t2, M);

    const float* c = color_u + b * 4;
    float theta = (c[0] * 2.f - 1.f) * (10.f * DEG);
    float cth = cosf(theta), sth = sinf(theta);
    const float a = 0.5773502691896258f;
    float K[9] = {0, -a, a, a, 0, -a, -a, a, 0};
    float Rh[9];
#pragma unroll
    for (int i = 0; i < 3; i++)
#pragma unroll
        for (int j = 0; j < 3; j++)
            Rh[i * 3 + j] = cth * (i == j ? 1.f : 0.f) + sth * K[i * 3 + j] +
                            (1.f - cth) * (1.f / 3.f);
    float sat = 1.f + (c[1] * 2.f - 1.f) * 0.4f;
    const float lum[3] = {0.299f, 0.587f, 0.114f};
    float Sm[9];
#pragma unroll
    for (int i = 0; i < 3; i++)
#pragma unroll
        for (int j = 0; j < 3; j++)
            Sm[i * 3 + j] = sat * (i == j ? 1.f : 0.f) + (1.f - sat) * lum[j];
    float bright = 1.f + (c[2] * 2.f - 1.f) * 0.1f;
    float Mc[9];
    mat3_mul(Sm, Rh, Mc);
#pragma unroll
    for (int i = 0; i < 9; i++) Mc[i] *= bright;
    float gamma = 1.f + (c[3] * 2.f - 1.f) * 0.2f;

    const float* cu = cutout_u + b * 5;
    float* p = g_params + b * 32;
#pragma unroll
    for (int i = 0; i < 9; i++) p[i] = M[i];
    p[9] = gamma;
#pragma unroll
    for (int i = 0; i < 9; i++) p[10 + i] = Mc[i];
    p[19] = (cu[0] < 0.5f) ? 1.f : 0.f;
    p[20] = cu[1];
    p[21] = cu[2];
    p[22] = (0.3f + 0.2f * cu[3]) * 0.5f;
    p[23] = (0.3f + 0.2f * cu[4]) * 0.5f;
}

__global__ __launch_bounds__(NT) void augment_main(
    const float* __restrict__ images, float* __restrict__ out) {
    __shared__ float spm[24];

    int b   = blockIdx.z;
    int tid = threadIdx.x;
    if (tid < 24) spm[tid] = g_params[b * 32 + tid];
    __syncthreads();

    int lane = tid & 31;
    int w    = tid >> 5;
    int jx   = (blockIdx.x << 5) + lane;       // x
    int iy0  = (blockIdx.y << 5) + (w << 2);   // first of 4 rows

    // params -> registers (one LDS burst per thread, amortized over 4 px)
    float m0 = spm[0], m1 = spm[1], m2 = spm[2];
    float m3 = spm[3], m4 = spm[4], m5 = spm[5];
    float m6 = spm[6], m7 = spm[7], m8 = spm[8];
    float gamma = spm[9];
    float c0 = spm[10], c1 = spm[11], c2 = spm[12];
    float c3 = spm[13], c4 = spm[14], c5 = spm[15];
    float c6 = spm[16], c7 = spm[17], c8 = spm[18];
    float capply = spm[19], ccx = spm[20], ccy = spm[21];
    float cwh = spm[22], chh = spm[23];

    const float cc = 2.f / 511.f;
    float X = (float)jx * cc - 1.f;
    float sxX = fmaf(m0, X, m2);
    float syX = fmaf(m3, X, m5);
    float szX = fmaf(m6, X, m8);

    float gx = (float)jx * (1.f / 511.f);
    bool cutx = (capply != 0.f) & (fabsf(gx - ccx) < cwh);

    int bOff = b << 18;                        // pixel offset of image b
    int outBase = ((bOff + (iy0 << 9)) + jx) * 3;

#pragma unroll
    for (int k = 0; k < 4; k++) {
        int iy = iy0 + k;
        float Y = (float)iy * cc - 1.f;

        float sx = fmaf(m1, Y, sxX);
        float sy = fmaf(m4, Y, syX);
        float sz = fmaf(m7, Y, szX);
        float inv = frcp_nr(sz);
        float px = fmaf(sx * inv, 255.5f, 255.5f);
        float py = fmaf(sy * inv, 255.5f, 255.5f);

        bool valid = (px >= 0.f) & (px <= 511.f) & (py >= 0.f) & (py <= 511.f);
        float fx0 = fminf(fmaxf(floorf(px), 0.f), 511.f);
        float fy0 = fminf(fmaxf(floorf(py), 0.f), 511.f);
        float wx = px - fx0;
        float wy = py - fy0;
        int x0 = (int)fx0, y0 = (int)fy0;
        int dx3 = (x0 < 511) ? 3 : 0;
        int dyW = (y0 < 511) ? (W_ * 3) : 0;

        const float* A = images + (bOff + (y0 << 9) + x0) * 3;
        const float* Bt = A + dyW;

        float a00 = __ldg(A + 0),        a01 = __ldg(A + 1),        a02 = __ldg(A + 2);
        float b00 = __ldg(A + dx3 + 0),  b01 = __ldg(A + dx3 + 1),  b02 = __ldg(A + dx3 + 2);
        float d00 = __ldg(Bt + 0),       d01 = __ldg(Bt + 1),       d02 = __ldg(Bt + 2);
        float e00 = __ldg(Bt + dx3 + 0), e01 = __ldg(Bt + dx3 + 1), e02 = __ldg(Bt + dx3 + 2);

        float omx = 1.f - wx, omy = 1.f - wy;
        float w00 = omx * omy, w01 = wx * omy, w10 = omx * wy, w11 = wx * wy;
        float vm = valid ? 1.f : 0.f;

        float r0 = a00 * w00 + b00 * w01 + d00 * w10 + e00 * w11;
        float r1 = a01 * w00 + b01 * w01 + d01 * w10 + e01 * w11;
        float r2 = a02 * w00 + b02 * w01 + d02 * w10 + e02 * w11;
        r0 = fminf(fmaxf(r0 * vm, 0.f), 1.f);
        r1 = fminf(fmaxf(r1 * vm, 0.f), 1.f);
        r2 = fminf(fmaxf(r2 * vm, 0.f), 1.f);
        r0 = fex2(gamma * flg2(r0));   // 0 -> ex2(-inf) = 0 == 0^g
        r1 = fex2(gamma * flg2(r1));
        r2 = fex2(gamma * flg2(r2));

        float o0 = c0 * r0 + c1 * r1 + c2 * r2;
        float o1 = c3 * r0 + c4 * r1 + c5 * r2;
        float o2 = c6 * r0 + c7 * r1 + c8 * r2;
        o0 = fminf(fmaxf(o0, 0.f), 1.f);
        o1 = fminf(fmaxf(o1, 0.f), 1.f);
        o2 = fminf(fmaxf(o2, 0.f), 1.f);

        float gy = (float)iy * (1.f / 511.f);
        bool cut = cutx & (fabsf(gy - ccy) < chh);
        if (cut) { o0 = 0.f; o1 = 0.f; o2 = 0.f; }

        float* op = out + outBase + k * (W_ * 3);
        op[0] = o0;
        op[1] = o1;
        op[2] = o2;
    }
}

extern "C" void kernel_launch(void* const* d_in, const int* in_sizes, int n_in,
                              void* d_out, int out_size) {
    const float* images   = (const float*)d_in[0];
    const float* geom_u   = (const float*)d_in[1];
    const float* color_u  = (const float*)d_in[2];
    const float* cutout_u = (const float*)d_in[3];
    float* out = (float*)d_out;

    param_kernel<<<1, 32>>>(geom_u, color_u, cutout_u);
    dim3 grid(W_ / 32, H_ / 32, B_);
    augment_main<<<grid, NT>>>(images, out);
}

// round 8
// speedup vs baseline: 2.0363x; 1.0161x over previous
#include <cuda_runtime.h>
#include <math.h>

#define B_  32
#define H_  512
#define W_  512
#define DEG 0.017453292519943295f
#define NT  256     // 8 warps; warp w handles rows [w*4, w*4+4) of a 32x32 tile

__device__ float g_params[B_ * 32];

__device__ __forceinline__ float frcp_nr(float x) {
    float y;
    asm("rcp.approx.f32 %0, %1;" : "=f"(y) : "f"(x));
    return y * fmaf(-x, y, 2.0f);   // one Newton step -> ~1 ulp
}
__device__ __forceinline__ float flg2(float x) {
    float y;
    asm("lg2.approx.f32 %0, %1;" : "=f"(y) : "f"(x));
    return y;
}
__device__ __forceinline__ float fex2(float x) {
    float y;
    asm("ex2.approx.f32 %0, %1;" : "=f"(y) : "f"(x));
    return y;
}

__device__ __forceinline__ void mat3_mul(const float* A, const float* Bm, float* C) {
#pragma unroll
    for (int i = 0; i < 3; i++)
#pragma unroll
        for (int j = 0; j < 3; j++) {
            float s = 0.f;
#pragma unroll
            for (int k = 0; k < 3; k++) s += A[i * 3 + k] * Bm[k * 3 + j];
            C[i * 3 + j] = s;
        }
}

__global__ void param_kernel(const float* __restrict__ geom_u,
                             const float* __restrict__ color_u,
                             const float* __restrict__ cutout_u) {
    int b = threadIdx.x;
    if (b >= B_) return;

    const float* g = geom_u + b * 8;
    float flip = g[0] > 0.5f ? -1.f : 1.f;
    float tilt = (g[1] * 2.f - 1.f) * (15.f * DEG);
    float pan  = (g[2] * 2.f - 1.f) * (15.f * DEG);
    float rot  = (g[3] * 2.f - 1.f) * (15.f * DEG);
    float sc   = 1.f + (g[4] * 2.f - 1.f) * 0.1f;
    float tx   = (g[5] * 2.f - 1.f) * 0.2f;
    float ty   = (g[6] * 2.f - 1.f) * 0.2f;

    float F[9]  = {flip, 0, 0, 0, 1, 0, 0, 0, 1};
    float ct = cosf(tilt), st = sinf(tilt);
    float Rx[9] = {1, 0, 0, 0, ct, -st, 0, st, ct};
    float cp = cosf(pan), sp = sinf(pan);
    float Ry[9] = {cp, 0, sp, 0, 1, 0, -sp, 0, cp};
    float cr = cosf(rot), sr = sinf(rot);
    float RS[9] = {sc * cr, -sc * sr, 0, sc * sr, sc * cr, 0, 0, 0, 1};
    float T[9]  = {1, 0, tx, 0, 1, ty, 0, 0, 1};

    float t0[9], t1[9], t2[9], M[9];
    mat3_mul(Ry, F, t0);
    mat3_mul(Rx, t0, t1);
    mat3_mul(RS, t1, t2);
    mat3_mul(T, t2, M);

    const float* c = color_u + b * 4;
    float theta = (c[0] * 2.f - 1.f) * (10.f * DEG);
    float cth = cosf(theta), sth = sinf(theta);
    const float a = 0.5773502691896258f;
    float K[9] = {0, -a, a, a, 0, -a, -a, a, 0};
    float Rh[9];
#pragma unroll
    for (int i = 0; i < 3; i++)
#pragma unroll
        for (int j = 0; j < 3; j++)
            Rh[i * 3 + j] = cth * (i == j ? 1.f : 0.f) + sth * K[i * 3 + j] +
                            (1.f - cth) * (1.f / 3.f);
    float sat = 1.f + (c[1] * 2.f - 1.f) * 0.4f;
    const float lum[3] = {0.299f, 0.587f, 0.114f};
    float Sm[9];
#pragma unroll
    for (int i = 0; i < 3; i++)
#pragma unroll
        for (int j = 0; j < 3; j++)
            Sm[i * 3 + j] = sat * (i == j ? 1.f : 0.f) + (1.f - sat) * lum[j];
    float bright = 1.f + (c[2] * 2.f - 1.f) * 0.1f;
    float Mc[9];
    mat3_mul(Sm, Rh, Mc);
#pragma unroll
    for (int i = 0; i < 9; i++) Mc[i] *= bright;
    float gamma = 1.f + (c[3] * 2.f - 1.f) * 0.2f;

    const float* cu = cutout_u + b * 5;
    float* p = g_params + b * 32;
#pragma unroll
    for (int i = 0; i < 9; i++) p[i] = M[i];
    p[9] = gamma;
#pragma unroll
    for (int i = 0; i < 9; i++) p[10 + i] = Mc[i];
    p[19] = (cu[0] < 0.5f) ? 1.f : 0.f;
    p[20] = cu[1];
    p[21] = cu[2];
    p[22] = (0.3f + 0.2f * cu[3]) * 0.5f;
    p[23] = (0.3f + 0.2f * cu[4]) * 0.5f;
}

__global__ __launch_bounds__(NT, 6) void augment_main(
    const float* __restrict__ images, float* __restrict__ out) {
    __shared__ float spm[24];

    int b   = blockIdx.z;
    int tid = threadIdx.x;
    if (tid < 24) spm[tid] = g_params[b * 32 + tid];
    __syncthreads();

    int lane = tid & 31;
    int w    = tid >> 5;
    int jx   = (blockIdx.x << 5) + lane;       // x
    int iy0  = (blockIdx.y << 5) + (w << 2);   // first of 4 rows

    float m0 = spm[0], m1 = spm[1], m2 = spm[2];
    float m3 = spm[3], m4 = spm[4], m5 = spm[5];
    float m6 = spm[6], m7 = spm[7], m8 = spm[8];
    float gamma = spm[9];
    float c0 = spm[10], c1 = spm[11], c2 = spm[12];
    float c3 = spm[13], c4 = spm[14], c5 = spm[15];
    float c6 = spm[16], c7 = spm[17], c8 = spm[18];
    float capply = spm[19], ccx = spm[20], ccy = spm[21];
    float cwh = spm[22], chh = spm[23];

    const float cc = 2.f / 511.f;
    float X = (float)jx * cc - 1.f;
    float sxX = fmaf(m0, X, m2);
    float syX = fmaf(m3, X, m5);
    float szX = fmaf(m6, X, m8);

    float gx = (float)jx * (1.f / 511.f);
    bool cutx = (capply != 0.f) & (fabsf(gx - ccx) < cwh);

    int bOff = b << 18;
    int outBase = ((bOff + (iy0 << 9)) + jx) * 3;

#pragma unroll
    for (int k = 0; k < 4; k++) {
        int iy = iy0 + k;
        float Y = (float)iy * cc - 1.f;

        float sx = fmaf(m1, Y, sxX);
        float sy = fmaf(m4, Y, syX);
        float sz = fmaf(m7, Y, szX);
        float inv = frcp_nr(sz);
        float px = fmaf(sx * inv, 255.5f, 255.5f);
        float py = fmaf(sy * inv, 255.5f, 255.5f);

        bool valid = (px >= 0.f) & (px <= 511.f) & (py >= 0.f) & (py <= 511.f);
        int x0 = min(max(__float2int_rd(px), 0), 511);
        int y0 = min(max(__float2int_rd(py), 0), 511);
        float wx = px - (float)x0;       // exact for valid lanes; garbage*0 otherwise
        float wy = py - (float)y0;
        int dx3 = (x0 < 511) ? 3 : 0;
        int dyW = (y0 < 511) ? (W_ * 3) : 0;

        const float* A = images + (bOff + (y0 << 9) + x0) * 3;
        const float* Bt = A + dyW;

        float a00 = __ldg(A + 0),        a01 = __ldg(A + 1),        a02 = __ldg(A + 2);
        float b00 = __ldg(A + dx3 + 0),  b01 = __ldg(A + dx3 + 1),  b02 = __ldg(A + dx3 + 2);
        float d00 = __ldg(Bt + 0),       d01 = __ldg(Bt + 1),       d02 = __ldg(Bt + 2);
        float e00 = __ldg(Bt + dx3 + 0), e01 = __ldg(Bt + dx3 + 1), e02 = __ldg(Bt + dx3 + 2);

        float omx = 1.f - wx, omy = 1.f - wy;
        float w00 = omx * omy, w01 = wx * omy, w10 = omx * wy, w11 = wx * wy;
        float vm = valid ? 1.f : 0.f;

        float r0 = a00 * w00 + b00 * w01 + d00 * w10 + e00 * w11;
        float r1 = a01 * w00 + b01 * w01 + d01 * w10 + e01 * w11;
        float r2 = a02 * w00 + b02 * w01 + d02 * w10 + e02 * w11;
        // taps/weights >= 0 so r >= 0: only upper clamp needed
        r0 = fminf(r0 * vm, 1.f);
        r1 = fminf(r1 * vm, 1.f);
        r2 = fminf(r2 * vm, 1.f);
        r0 = fex2(gamma * flg2(r0));   // 0 -> ex2(-inf) = 0 == 0^g
        r1 = fex2(gamma * flg2(r1));
        r2 = fex2(gamma * flg2(r2));

        float o0 = c0 * r0 + c1 * r1 + c2 * r2;
        float o1 = c3 * r0 + c4 * r1 + c5 * r2;
        float o2 = c6 * r0 + c7 * r1 + c8 * r2;
        o0 = fminf(fmaxf(o0, 0.f), 1.f);
        o1 = fminf(fmaxf(o1, 0.f), 1.f);
        o2 = fminf(fmaxf(o2, 0.f), 1.f);

        float gy = (float)iy * (1.f / 511.f);
        bool cut = cutx & (fabsf(gy - ccy) < chh);
        if (cut) { o0 = 0.f; o1 = 0.f; o2 = 0.f; }

        float* op = out + outBase + k * (W_ * 3);
        op[0] = o0;
        op[1] = o1;
        op[2] = o2;
    }
}

extern "C" void kernel_launch(void* const* d_in, const int* in_sizes, int n_in,
                              void* d_out, int out_size) {
    const float* images   = (const float*)d_in[0];
    const float* geom_u   = (const float*)d_in[1];
    const float* color_u  = (const float*)d_in[2];
    const float* cutout_u = (const float*)d_in[3];
    float* out = (float*)d_out;

    param_kernel<<<1, 32>>>(geom_u, color_u, cutout_u);
    dim3 grid(W_ / 32, H_ / 32, B_);
    augment_main<<<grid, NT>>>(images, out);
}